// round 1
// baseline (speedup 1.0000x reference)
#include <cuda_runtime.h>
#include <cstdint>

// Problem constants
#define N_TOK  32768     // B*Q
#define H_DIM  1024
#define HR_DIM 512
#define CB_N   4096

// GEMM tiling
#define BM 128
#define BN 128
#define BK 16

// ---------------- scratch (device globals; no runtime allocation) ----------------
__device__ float g_h[(size_t)N_TOK * H_DIM];   // 134 MB: h (enc) then h2 (dec)
__device__ float g_z[(size_t)N_TOK * HR_DIM];  // 67 MB: pre-quant latent
__device__ float g_cbnorm[CB_N];               // ||e_c||^2
__device__ unsigned long long g_best[N_TOK];   // packed (ordered_d_key<<32 | idx)
__device__ float g_commit[N_TOK];              // per-row commit partial sums

// Monotonic float->uint mapping so unsigned compare == float compare
__device__ __forceinline__ unsigned long long pack_di(float d, unsigned idx) {
    unsigned b = __float_as_uint(d);
    unsigned key = b ^ ((unsigned)((int)b >> 31) | 0x80000000u);
    return ((unsigned long long)key << 32) | (unsigned long long)idx;
}

// ---------------- SGEMM: C[M,N] = op(A[M,K] @ B[K,N] + bias), op = relu? ----------------
// 256 threads, 128x128 tile, BK=16, 8x8 per thread, double-buffered smem.
template<bool RELU>
__global__ __launch_bounds__(256, 2)
void sgemm_kernel(const float* __restrict__ A, const float* __restrict__ B,
                  const float* __restrict__ bias, float* __restrict__ C,
                  int M, int N, int K)
{
    __shared__ __align__(16) float As[2][BK][BM];
    __shared__ __align__(16) float Bs[2][BK][BN];

    const int tid = threadIdx.x;
    const int bm = blockIdx.y * BM;
    const int bn = blockIdx.x * BN;
    const int tx = tid & 15;   // 16 col groups
    const int ty = tid >> 4;   // 16 row groups

    // A tile loads: 128x16 floats = 512 float4; 2 per thread.
    const int a_r = tid >> 2;          // 0..63 (+64 for second)
    const int a_k = (tid & 3) * 4;     // 0,4,8,12
    // B tile loads: 16x128 floats = 512 float4; 2 per thread.
    const int b_r = tid >> 5;          // 0..7 (+8 for second)
    const int b_c = (tid & 31) * 4;    // 0..124

    const float* Ap0 = A + (size_t)(bm + a_r)      * K + a_k;
    const float* Ap1 = A + (size_t)(bm + a_r + 64) * K + a_k;
    const float* Bp0 = B + (size_t)(b_r)     * N + bn + b_c;
    const float* Bp1 = B + (size_t)(b_r + 8) * N + bn + b_c;

    float acc[8][8];
    #pragma unroll
    for (int i = 0; i < 8; i++)
        #pragma unroll
        for (int j = 0; j < 8; j++) acc[i][j] = 0.0f;

    // prologue: tile 0
    float4 ar0 = *(const float4*)Ap0;
    float4 ar1 = *(const float4*)Ap1;
    float4 br0 = *(const float4*)Bp0;
    float4 br1 = *(const float4*)Bp1;

    As[0][a_k+0][a_r] = ar0.x;  As[0][a_k+1][a_r] = ar0.y;
    As[0][a_k+2][a_r] = ar0.z;  As[0][a_k+3][a_r] = ar0.w;
    As[0][a_k+0][a_r+64] = ar1.x;  As[0][a_k+1][a_r+64] = ar1.y;
    As[0][a_k+2][a_r+64] = ar1.z;  As[0][a_k+3][a_r+64] = ar1.w;
    *(float4*)&Bs[0][b_r][b_c]   = br0;
    *(float4*)&Bs[0][b_r+8][b_c] = br1;
    __syncthreads();

    const int nK = K / BK;
    int cur = 0;
    for (int kt = 0; kt < nK; kt++) {
        if (kt + 1 < nK) {
            const size_t koff = (size_t)(kt + 1) * BK;
            ar0 = *(const float4*)(Ap0 + koff);
            ar1 = *(const float4*)(Ap1 + koff);
            br0 = *(const float4*)(Bp0 + koff * N);
            br1 = *(const float4*)(Bp1 + koff * N);
        }
        #pragma unroll
        for (int k = 0; k < BK; k++) {
            float a[8], b[8];
            *(float4*)&a[0] = *(const float4*)&As[cur][k][ty*8];
            *(float4*)&a[4] = *(const float4*)&As[cur][k][ty*8+4];
            *(float4*)&b[0] = *(const float4*)&Bs[cur][k][tx*8];
            *(float4*)&b[4] = *(const float4*)&Bs[cur][k][tx*8+4];
            #pragma unroll
            for (int i = 0; i < 8; i++)
                #pragma unroll
                for (int j = 0; j < 8; j++)
                    acc[i][j] = fmaf(a[i], b[j], acc[i][j]);
        }
        if (kt + 1 < nK) {
            const int nxt = cur ^ 1;
            As[nxt][a_k+0][a_r] = ar0.x;  As[nxt][a_k+1][a_r] = ar0.y;
            As[nxt][a_k+2][a_r] = ar0.z;  As[nxt][a_k+3][a_r] = ar0.w;
            As[nxt][a_k+0][a_r+64] = ar1.x;  As[nxt][a_k+1][a_r+64] = ar1.y;
            As[nxt][a_k+2][a_r+64] = ar1.z;  As[nxt][a_k+3][a_r+64] = ar1.w;
            *(float4*)&Bs[nxt][b_r][b_c]   = br0;
            *(float4*)&Bs[nxt][b_r+8][b_c] = br1;
            __syncthreads();
            cur = nxt;
        }
    }

    // epilogue: bias (+relu), vectorized store
    #pragma unroll
    for (int i = 0; i < 8; i++) {
        const size_t rowoff = (size_t)(bm + ty*8 + i) * N;
        #pragma unroll
        for (int j = 0; j < 8; j += 4) {
            const int col = bn + tx*8 + j;
            float4 v;
            v.x = acc[i][j+0] + bias[col+0];
            v.y = acc[i][j+1] + bias[col+1];
            v.z = acc[i][j+2] + bias[col+2];
            v.w = acc[i][j+3] + bias[col+3];
            if (RELU) {
                v.x = fmaxf(v.x, 0.0f); v.y = fmaxf(v.y, 0.0f);
                v.z = fmaxf(v.z, 0.0f); v.w = fmaxf(v.w, 0.0f);
            }
            *(float4*)&C[rowoff + col] = v;
        }
    }
}

// ---------------- VQ: fused NT-GEMM (z @ codebook^T) + argmin epilogue ----------------
// A = z [N_TOK, HR], B = codebook [CB_N, HR] (reduction along last dim of both).
__global__ __launch_bounds__(256, 2)
void vq_kernel(const float* __restrict__ Z, const float* __restrict__ CB)
{
    __shared__ __align__(16) float As[2][BK][BM];
    __shared__ __align__(16) float Bs[2][BK][BN];
    __shared__ unsigned long long red[BM];

    const int tid = threadIdx.x;
    const int bm = blockIdx.y * BM;   // token tile
    const int bn = blockIdx.x * BN;   // codebook tile
    const int tx = tid & 15;
    const int ty = tid >> 4;

    const int a_r = tid >> 2;
    const int a_k = (tid & 3) * 4;

    const float* Ap0 = Z  + (size_t)(bm + a_r)      * HR_DIM + a_k;
    const float* Ap1 = Z  + (size_t)(bm + a_r + 64) * HR_DIM + a_k;
    const float* Bp0 = CB + (size_t)(bn + a_r)      * HR_DIM + a_k;
    const float* Bp1 = CB + (size_t)(bn + a_r + 64) * HR_DIM + a_k;

    if (tid < BM) red[tid] = 0xFFFFFFFFFFFFFFFFull;

    float acc[8][8];
    #pragma unroll
    for (int i = 0; i < 8; i++)
        #pragma unroll
        for (int j = 0; j < 8; j++) acc[i][j] = 0.0f;

    float4 ar0 = *(const float4*)Ap0;
    float4 ar1 = *(const float4*)Ap1;
    float4 br0 = *(const float4*)Bp0;
    float4 br1 = *(const float4*)Bp1;

    As[0][a_k+0][a_r] = ar0.x;  As[0][a_k+1][a_r] = ar0.y;
    As[0][a_k+2][a_r] = ar0.z;  As[0][a_k+3][a_r] = ar0.w;
    As[0][a_k+0][a_r+64] = ar1.x;  As[0][a_k+1][a_r+64] = ar1.y;
    As[0][a_k+2][a_r+64] = ar1.z;  As[0][a_k+3][a_r+64] = ar1.w;
    Bs[0][a_k+0][a_r] = br0.x;  Bs[0][a_k+1][a_r] = br0.y;
    Bs[0][a_k+2][a_r] = br0.z;  Bs[0][a_k+3][a_r] = br0.w;
    Bs[0][a_k+0][a_r+64] = br1.x;  Bs[0][a_k+1][a_r+64] = br1.y;
    Bs[0][a_k+2][a_r+64] = br1.z;  Bs[0][a_k+3][a_r+64] = br1.w;
    __syncthreads();

    const int nK = HR_DIM / BK;   // 32
    int cur = 0;
    for (int kt = 0; kt < nK; kt++) {
        if (kt + 1 < nK) {
            const size_t koff = (size_t)(kt + 1) * BK;
            ar0 = *(const float4*)(Ap0 + koff);
            ar1 = *(const float4*)(Ap1 + koff);
            br0 = *(const float4*)(Bp0 + koff);
            br1 = *(const float4*)(Bp1 + koff);
        }
        #pragma unroll
        for (int k = 0; k < BK; k++) {
            float a[8], b[8];
            *(float4*)&a[0] = *(const float4*)&As[cur][k][ty*8];
            *(float4*)&a[4] = *(const float4*)&As[cur][k][ty*8+4];
            *(float4*)&b[0] = *(const float4*)&Bs[cur][k][tx*8];
            *(float4*)&b[4] = *(const float4*)&Bs[cur][k][tx*8+4];
            #pragma unroll
            for (int i = 0; i < 8; i++)
                #pragma unroll
                for (int j = 0; j < 8; j++)
                    acc[i][j] = fmaf(a[i], b[j], acc[i][j]);
        }
        if (kt + 1 < nK) {
            const int nxt = cur ^ 1;
            As[nxt][a_k+0][a_r] = ar0.x;  As[nxt][a_k+1][a_r] = ar0.y;
            As[nxt][a_k+2][a_r] = ar0.z;  As[nxt][a_k+3][a_r] = ar0.w;
            As[nxt][a_k+0][a_r+64] = ar1.x;  As[nxt][a_k+1][a_r+64] = ar1.y;
            As[nxt][a_k+2][a_r+64] = ar1.z;  As[nxt][a_k+3][a_r+64] = ar1.w;
            Bs[nxt][a_k+0][a_r] = br0.x;  Bs[nxt][a_k+1][a_r] = br0.y;
            Bs[nxt][a_k+2][a_r] = br0.z;  Bs[nxt][a_k+3][a_r] = br0.w;
            Bs[nxt][a_k+0][a_r+64] = br1.x;  Bs[nxt][a_k+1][a_r+64] = br1.y;
            Bs[nxt][a_k+2][a_r+64] = br1.z;  Bs[nxt][a_k+3][a_r+64] = br1.w;
            __syncthreads();
            cur = nxt;
        }
    }

    // epilogue: d = ||e||^2 - 2*(z.e); per-row argmin (first-occurrence ties)
    float cn[8];
    #pragma unroll
    for (int j = 0; j < 8; j++) cn[j] = __ldg(&g_cbnorm[bn + tx*8 + j]);

    #pragma unroll
    for (int i = 0; i < 8; i++) {
        float bestd = cn[0] - 2.0f * acc[i][0];
        int   bestj = 0;
        #pragma unroll
        for (int j = 1; j < 8; j++) {
            float d = cn[j] - 2.0f * acc[i][j];
            if (d < bestd) { bestd = d; bestj = j; }
        }
        atomicMin(&red[ty*8 + i], pack_di(bestd, (unsigned)(bn + tx*8 + bestj)));
    }
    __syncthreads();
    if (tid < BM) atomicMin(&g_best[bm + tid], red[tid]);
}

// ---------------- codebook norms + argmin state init ----------------
__global__ void prep_kernel(const float* __restrict__ CB)
{
    const int row = blockIdx.x;      // CB_N blocks
    const int tid = threadIdx.x;     // 128 threads -> 128 float4 = 512 floats
    float4 v = ((const float4*)(CB + (size_t)row * HR_DIM))[tid];
    float s = v.x*v.x + v.y*v.y + v.z*v.z + v.w*v.w;
    #pragma unroll
    for (int o = 16; o; o >>= 1) s += __shfl_down_sync(0xFFFFFFFFu, s, o);
    __shared__ float ws[4];
    if ((tid & 31) == 0) ws[tid >> 5] = s;
    __syncthreads();
    if (tid == 0) g_cbnorm[row] = ws[0] + ws[1] + ws[2] + ws[3];

    const int g = row * 128 + tid;   // 524288 slots cover N_TOK
    if (g < N_TOK) g_best[g] = 0xFFFFFFFFFFFFFFFFull;
}

// ---------------- gather winner codebook row + per-row commit partial ----------------
__global__ void gather_kernel(const float* __restrict__ CB,
                              float* __restrict__ outq, float* __restrict__ outidx)
{
    const int row = blockIdx.x;      // N_TOK blocks
    const int tid = threadIdx.x;     // 128 threads
    const unsigned idx = (unsigned)(g_best[row] & 0xFFFFFFFFull);

    float4 ev = ((const float4*)(CB  + (size_t)idx * HR_DIM))[tid];
    float4 zv = ((const float4*)(g_z + (size_t)row * HR_DIM))[tid];
    ((float4*)(outq + (size_t)row * HR_DIM))[tid] = ev;

    const float dx = zv.x - ev.x, dy = zv.y - ev.y;
    const float dz = zv.z - ev.z, dw = zv.w - ev.w;
    float s = dx*dx + dy*dy + dz*dz + dw*dw;
    #pragma unroll
    for (int o = 16; o; o >>= 1) s += __shfl_down_sync(0xFFFFFFFFu, s, o);
    __shared__ float ws[4];
    if ((tid & 31) == 0) ws[tid >> 5] = s;
    __syncthreads();
    if (tid == 0) {
        g_commit[row] = ws[0] + ws[1] + ws[2] + ws[3];
        outidx[row] = (float)idx;
    }
}

// ---------------- deterministic commit-loss reduce ----------------
__global__ void loss_kernel(float* __restrict__ out_loss)
{
    __shared__ float ws[32];
    const int tid = threadIdx.x;     // 1024
    float s = 0.0f;
    for (int i = tid; i < N_TOK; i += 1024) s += g_commit[i];
    #pragma unroll
    for (int o = 16; o; o >>= 1) s += __shfl_down_sync(0xFFFFFFFFu, s, o);
    if ((tid & 31) == 0) ws[tid >> 5] = s;
    __syncthreads();
    if (tid < 32) {
        float t = ws[tid];
        #pragma unroll
        for (int o = 16; o; o >>= 1) t += __shfl_down_sync(0xFFFFFFFFu, t, o);
        if (tid == 0)
            out_loss[0] = 0.25f * t / (float)((size_t)N_TOK * HR_DIM);
    }
}

// ---------------- launcher ----------------
extern "C" void kernel_launch(void* const* d_in, const int* in_sizes, int n_in,
                              void* d_out, int out_size)
{
    const float* x      = (const float*)d_in[0];
    const float* enc_w1 = (const float*)d_in[1];
    const float* enc_b1 = (const float*)d_in[2];
    const float* enc_w2 = (const float*)d_in[3];
    const float* enc_b2 = (const float*)d_in[4];
    const float* cb     = (const float*)d_in[5];
    const float* dec_w1 = (const float*)d_in[6];
    const float* dec_b1 = (const float*)d_in[7];
    const float* dec_w2 = (const float*)d_in[8];
    const float* dec_b2 = (const float*)d_in[9];

    float* out       = (float*)d_out;
    float* out_recon = out;                                        // [B,Q,H]
    float* out_q     = out_recon + (size_t)N_TOK * H_DIM;          // [B,Q,HR]
    float* out_idx   = out_q + (size_t)N_TOK * HR_DIM;             // [B,Q]
    float* out_loss  = out_idx + N_TOK;                            // scalar

    float *h, *z;
    cudaGetSymbolAddress((void**)&h, g_h);
    cudaGetSymbolAddress((void**)&z, g_z);

    // codebook norms + argmin init
    prep_kernel<<<CB_N, 128>>>(cb);

    // encoder
    sgemm_kernel<true ><<<dim3(H_DIM/BN,  N_TOK/BM), 256>>>(x, enc_w1, enc_b1, h, N_TOK, H_DIM,  H_DIM);
    sgemm_kernel<false><<<dim3(HR_DIM/BN, N_TOK/BM), 256>>>(h, enc_w2, enc_b2, z, N_TOK, HR_DIM, H_DIM);

    // vector-quantize: fused distance GEMM + argmin
    vq_kernel<<<dim3(CB_N/BN, N_TOK/BM), 256>>>(z, cb);
    gather_kernel<<<N_TOK, 128>>>(cb, out_q, out_idx);

    // decoder (input = quantized_st == gathered codebook rows)
    sgemm_kernel<true ><<<dim3(H_DIM/BN, N_TOK/BM), 256>>>(out_q, dec_w1, dec_b1, h, N_TOK, H_DIM, HR_DIM);
    sgemm_kernel<false><<<dim3(H_DIM/BN, N_TOK/BM), 256>>>(h, dec_w2, dec_b2, out_recon, N_TOK, H_DIM, H_DIM);

    // commit loss
    loss_kernel<<<1, 1024>>>(out_loss);
}

// round 2
// speedup vs baseline: 1.0002x; 1.0002x over previous
#include <cuda_runtime.h>
#include <cstdint>

// Problem constants
#define N_TOK  32768     // B*Q
#define H_DIM  1024
#define HR_DIM 512
#define CB_N   4096

// GEMM tiling
#define BM 128
#define BN 128
#define BK 16

// ---------------- scratch (device globals; no runtime allocation) ----------------
__device__ float g_h[(size_t)N_TOK * H_DIM];   // 134 MB: h (enc) then h2 (dec)
__device__ float g_z[(size_t)N_TOK * HR_DIM];  // 67 MB: pre-quant latent
__device__ float g_cbnorm[CB_N];               // ||e_c||^2
__device__ unsigned long long g_best[N_TOK];   // packed (ordered_d_key<<32 | idx)
__device__ float g_commit[N_TOK];              // per-row commit partial sums

// Monotonic float->uint mapping so unsigned compare == float compare
__device__ __forceinline__ unsigned long long pack_di(float d, unsigned idx) {
    unsigned b = __float_as_uint(d);
    unsigned key = b ^ ((unsigned)((int)b >> 31) | 0x80000000u);
    return ((unsigned long long)key << 32) | (unsigned long long)idx;
}

// ---------------- SGEMM: C[M,N] = op(A[M,K] @ B[K,N] + bias), op = relu? ----------------
// 256 threads, 128x128 tile, BK=16, 8x8 per thread, double-buffered smem.
template<bool RELU>
__global__ __launch_bounds__(256, 2)
void sgemm_kernel(const float* __restrict__ A, const float* __restrict__ B,
                  const float* __restrict__ bias, float* __restrict__ C,
                  int M, int N, int K)
{
    __shared__ __align__(16) float As[2][BK][BM];
    __shared__ __align__(16) float Bs[2][BK][BN];

    const int tid = threadIdx.x;
    const int bm = blockIdx.y * BM;
    const int bn = blockIdx.x * BN;
    const int tx = tid & 15;   // 16 col groups
    const int ty = tid >> 4;   // 16 row groups

    // A tile loads: 128x16 floats = 512 float4; 2 per thread.
    const int a_r = tid >> 2;          // 0..63 (+64 for second)
    const int a_k = (tid & 3) * 4;     // 0,4,8,12
    // B tile loads: 16x128 floats = 512 float4; 2 per thread.
    const int b_r = tid >> 5;          // 0..7 (+8 for second)
    const int b_c = (tid & 31) * 4;    // 0..124

    const float* Ap0 = A + (size_t)(bm + a_r)      * K + a_k;
    const float* Ap1 = A + (size_t)(bm + a_r + 64) * K + a_k;
    const float* Bp0 = B + (size_t)(b_r)     * N + bn + b_c;
    const float* Bp1 = B + (size_t)(b_r + 8) * N + bn + b_c;

    float acc[8][8];
    #pragma unroll
    for (int i = 0; i < 8; i++)
        #pragma unroll
        for (int j = 0; j < 8; j++) acc[i][j] = 0.0f;

    // prologue: tile 0
    float4 ar0 = *(const float4*)Ap0;
    float4 ar1 = *(const float4*)Ap1;
    float4 br0 = *(const float4*)Bp0;
    float4 br1 = *(const float4*)Bp1;

    As[0][a_k+0][a_r] = ar0.x;  As[0][a_k+1][a_r] = ar0.y;
    As[0][a_k+2][a_r] = ar0.z;  As[0][a_k+3][a_r] = ar0.w;
    As[0][a_k+0][a_r+64] = ar1.x;  As[0][a_k+1][a_r+64] = ar1.y;
    As[0][a_k+2][a_r+64] = ar1.z;  As[0][a_k+3][a_r+64] = ar1.w;
    *(float4*)&Bs[0][b_r][b_c]   = br0;
    *(float4*)&Bs[0][b_r+8][b_c] = br1;
    __syncthreads();

    const int nK = K / BK;
    int cur = 0;
    for (int kt = 0; kt < nK; kt++) {
        if (kt + 1 < nK) {
            const size_t koff = (size_t)(kt + 1) * BK;
            ar0 = *(const float4*)(Ap0 + koff);
            ar1 = *(const float4*)(Ap1 + koff);
            br0 = *(const float4*)(Bp0 + koff * N);
            br1 = *(const float4*)(Bp1 + koff * N);
        }
        #pragma unroll
        for (int k = 0; k < BK; k++) {
            float a[8], b[8];
            *(float4*)&a[0] = *(const float4*)&As[cur][k][ty*8];
            *(float4*)&a[4] = *(const float4*)&As[cur][k][ty*8+4];
            *(float4*)&b[0] = *(const float4*)&Bs[cur][k][tx*8];
            *(float4*)&b[4] = *(const float4*)&Bs[cur][k][tx*8+4];
            #pragma unroll
            for (int i = 0; i < 8; i++)
                #pragma unroll
                for (int j = 0; j < 8; j++)
                    acc[i][j] = fmaf(a[i], b[j], acc[i][j]);
        }
        if (kt + 1 < nK) {
            const int nxt = cur ^ 1;
            As[nxt][a_k+0][a_r] = ar0.x;  As[nxt][a_k+1][a_r] = ar0.y;
            As[nxt][a_k+2][a_r] = ar0.z;  As[nxt][a_k+3][a_r] = ar0.w;
            As[nxt][a_k+0][a_r+64] = ar1.x;  As[nxt][a_k+1][a_r+64] = ar1.y;
            As[nxt][a_k+2][a_r+64] = ar1.z;  As[nxt][a_k+3][a_r+64] = ar1.w;
            *(float4*)&Bs[nxt][b_r][b_c]   = br0;
            *(float4*)&Bs[nxt][b_r+8][b_c] = br1;
            __syncthreads();
            cur = nxt;
        }
    }

    // epilogue: bias (+relu), vectorized store
    #pragma unroll
    for (int i = 0; i < 8; i++) {
        const size_t rowoff = (size_t)(bm + ty*8 + i) * N;
        #pragma unroll
        for (int j = 0; j < 8; j += 4) {
            const int col = bn + tx*8 + j;
            float4 v;
            v.x = acc[i][j+0] + bias[col+0];
            v.y = acc[i][j+1] + bias[col+1];
            v.z = acc[i][j+2] + bias[col+2];
            v.w = acc[i][j+3] + bias[col+3];
            if (RELU) {
                v.x = fmaxf(v.x, 0.0f); v.y = fmaxf(v.y, 0.0f);
                v.z = fmaxf(v.z, 0.0f); v.w = fmaxf(v.w, 0.0f);
            }
            *(float4*)&C[rowoff + col] = v;
        }
    }
}

// ---------------- VQ: fused NT-GEMM (z @ codebook^T) + argmin epilogue ----------------
// A = z [N_TOK, HR], B = codebook [CB_N, HR] (reduction along last dim of both).
__global__ __launch_bounds__(256, 2)
void vq_kernel(const float* __restrict__ Z, const float* __restrict__ CB)
{
    __shared__ __align__(16) float As[2][BK][BM];
    __shared__ __align__(16) float Bs[2][BK][BN];
    __shared__ unsigned long long red[BM];

    const int tid = threadIdx.x;
    const int bm = blockIdx.y * BM;   // token tile
    const int bn = blockIdx.x * BN;   // codebook tile
    const int tx = tid & 15;
    const int ty = tid >> 4;

    const int a_r = tid >> 2;
    const int a_k = (tid & 3) * 4;

    const float* Ap0 = Z  + (size_t)(bm + a_r)      * HR_DIM + a_k;
    const float* Ap1 = Z  + (size_t)(bm + a_r + 64) * HR_DIM + a_k;
    const float* Bp0 = CB + (size_t)(bn + a_r)      * HR_DIM + a_k;
    const float* Bp1 = CB + (size_t)(bn + a_r + 64) * HR_DIM + a_k;

    if (tid < BM) red[tid] = 0xFFFFFFFFFFFFFFFFull;

    float acc[8][8];
    #pragma unroll
    for (int i = 0; i < 8; i++)
        #pragma unroll
        for (int j = 0; j < 8; j++) acc[i][j] = 0.0f;

    float4 ar0 = *(const float4*)Ap0;
    float4 ar1 = *(const float4*)Ap1;
    float4 br0 = *(const float4*)Bp0;
    float4 br1 = *(const float4*)Bp1;

    As[0][a_k+0][a_r] = ar0.x;  As[0][a_k+1][a_r] = ar0.y;
    As[0][a_k+2][a_r] = ar0.z;  As[0][a_k+3][a_r] = ar0.w;
    As[0][a_k+0][a_r+64] = ar1.x;  As[0][a_k+1][a_r+64] = ar1.y;
    As[0][a_k+2][a_r+64] = ar1.z;  As[0][a_k+3][a_r+64] = ar1.w;
    Bs[0][a_k+0][a_r] = br0.x;  Bs[0][a_k+1][a_r] = br0.y;
    Bs[0][a_k+2][a_r] = br0.z;  Bs[0][a_k+3][a_r] = br0.w;
    Bs[0][a_k+0][a_r+64] = br1.x;  Bs[0][a_k+1][a_r+64] = br1.y;
    Bs[0][a_k+2][a_r+64] = br1.z;  Bs[0][a_k+3][a_r+64] = br1.w;
    __syncthreads();

    const int nK = HR_DIM / BK;   // 32
    int cur = 0;
    for (int kt = 0; kt < nK; kt++) {
        if (kt + 1 < nK) {
            const size_t koff = (size_t)(kt + 1) * BK;
            ar0 = *(const float4*)(Ap0 + koff);
            ar1 = *(const float4*)(Ap1 + koff);
            br0 = *(const float4*)(Bp0 + koff);
            br1 = *(const float4*)(Bp1 + koff);
        }
        #pragma unroll
        for (int k = 0; k < BK; k++) {
            float a[8], b[8];
            *(float4*)&a[0] = *(const float4*)&As[cur][k][ty*8];
            *(float4*)&a[4] = *(const float4*)&As[cur][k][ty*8+4];
            *(float4*)&b[0] = *(const float4*)&Bs[cur][k][tx*8];
            *(float4*)&b[4] = *(const float4*)&Bs[cur][k][tx*8+4];
            #pragma unroll
            for (int i = 0; i < 8; i++)
                #pragma unroll
                for (int j = 0; j < 8; j++)
                    acc[i][j] = fmaf(a[i], b[j], acc[i][j]);
        }
        if (kt + 1 < nK) {
            const int nxt = cur ^ 1;
            As[nxt][a_k+0][a_r] = ar0.x;  As[nxt][a_k+1][a_r] = ar0.y;
            As[nxt][a_k+2][a_r] = ar0.z;  As[nxt][a_k+3][a_r] = ar0.w;
            As[nxt][a_k+0][a_r+64] = ar1.x;  As[nxt][a_k+1][a_r+64] = ar1.y;
            As[nxt][a_k+2][a_r+64] = ar1.z;  As[nxt][a_k+3][a_r+64] = ar1.w;
            Bs[nxt][a_k+0][a_r] = br0.x;  Bs[nxt][a_k+1][a_r] = br0.y;
            Bs[nxt][a_k+2][a_r] = br0.z;  Bs[nxt][a_k+3][a_r] = br0.w;
            Bs[nxt][a_k+0][a_r+64] = br1.x;  Bs[nxt][a_k+1][a_r+64] = br1.y;
            Bs[nxt][a_k+2][a_r+64] = br1.z;  Bs[nxt][a_k+3][a_r+64] = br1.w;
            __syncthreads();
            cur = nxt;
        }
    }

    // epilogue: d = ||e||^2 - 2*(z.e); per-row argmin (first-occurrence ties)
    float cn[8];
    #pragma unroll
    for (int j = 0; j < 8; j++) cn[j] = __ldg(&g_cbnorm[bn + tx*8 + j]);

    #pragma unroll
    for (int i = 0; i < 8; i++) {
        float bestd = cn[0] - 2.0f * acc[i][0];
        int   bestj = 0;
        #pragma unroll
        for (int j = 1; j < 8; j++) {
            float d = cn[j] - 2.0f * acc[i][j];
            if (d < bestd) { bestd = d; bestj = j; }
        }
        atomicMin(&red[ty*8 + i], pack_di(bestd, (unsigned)(bn + tx*8 + bestj)));
    }
    __syncthreads();
    if (tid < BM) atomicMin(&g_best[bm + tid], red[tid]);
}

// ---------------- codebook norms + argmin state init ----------------
__global__ void prep_kernel(const float* __restrict__ CB)
{
    const int row = blockIdx.x;      // CB_N blocks
    const int tid = threadIdx.x;     // 128 threads -> 128 float4 = 512 floats
    float4 v = ((const float4*)(CB + (size_t)row * HR_DIM))[tid];
    float s = v.x*v.x + v.y*v.y + v.z*v.z + v.w*v.w;
    #pragma unroll
    for (int o = 16; o; o >>= 1) s += __shfl_down_sync(0xFFFFFFFFu, s, o);
    __shared__ float ws[4];
    if ((tid & 31) == 0) ws[tid >> 5] = s;
    __syncthreads();
    if (tid == 0) g_cbnorm[row] = ws[0] + ws[1] + ws[2] + ws[3];

    const int g = row * 128 + tid;   // 524288 slots cover N_TOK
    if (g < N_TOK) g_best[g] = 0xFFFFFFFFFFFFFFFFull;
}

// ---------------- gather winner codebook row + per-row commit partial ----------------
__global__ void gather_kernel(const float* __restrict__ CB,
                              float* __restrict__ outq, float* __restrict__ outidx)
{
    const int row = blockIdx.x;      // N_TOK blocks
    const int tid = threadIdx.x;     // 128 threads
    const unsigned idx = (unsigned)(g_best[row] & 0xFFFFFFFFull);

    float4 ev = ((const float4*)(CB  + (size_t)idx * HR_DIM))[tid];
    float4 zv = ((const float4*)(g_z + (size_t)row * HR_DIM))[tid];
    ((float4*)(outq + (size_t)row * HR_DIM))[tid] = ev;

    const float dx = zv.x - ev.x, dy = zv.y - ev.y;
    const float dz = zv.z - ev.z, dw = zv.w - ev.w;
    float s = dx*dx + dy*dy + dz*dz + dw*dw;
    #pragma unroll
    for (int o = 16; o; o >>= 1) s += __shfl_down_sync(0xFFFFFFFFu, s, o);
    __shared__ float ws[4];
    if ((tid & 31) == 0) ws[tid >> 5] = s;
    __syncthreads();
    if (tid == 0) {
        g_commit[row] = ws[0] + ws[1] + ws[2] + ws[3];
        outidx[row] = (float)idx;
    }
}

// ---------------- deterministic commit-loss reduce ----------------
__global__ void loss_kernel(float* __restrict__ out_loss)
{
    __shared__ float ws[32];
    const int tid = threadIdx.x;     // 1024
    float s = 0.0f;
    for (int i = tid; i < N_TOK; i += 1024) s += g_commit[i];
    #pragma unroll
    for (int o = 16; o; o >>= 1) s += __shfl_down_sync(0xFFFFFFFFu, s, o);
    if ((tid & 31) == 0) ws[tid >> 5] = s;
    __syncthreads();
    if (tid < 32) {
        float t = ws[tid];
        #pragma unroll
        for (int o = 16; o; o >>= 1) t += __shfl_down_sync(0xFFFFFFFFu, t, o);
        if (tid == 0)
            out_loss[0] = 0.25f * t / (float)((size_t)N_TOK * HR_DIM);
    }
}

// ---------------- launcher ----------------
extern "C" void kernel_launch(void* const* d_in, const int* in_sizes, int n_in,
                              void* d_out, int out_size)
{
    const float* x      = (const float*)d_in[0];
    const float* enc_w1 = (const float*)d_in[1];
    const float* enc_b1 = (const float*)d_in[2];
    const float* enc_w2 = (const float*)d_in[3];
    const float* enc_b2 = (const float*)d_in[4];
    const float* cb     = (const float*)d_in[5];
    const float* dec_w1 = (const float*)d_in[6];
    const float* dec_b1 = (const float*)d_in[7];
    const float* dec_w2 = (const float*)d_in[8];
    const float* dec_b2 = (const float*)d_in[9];

    float* out       = (float*)d_out;
    float* out_recon = out;                                        // [B,Q,H]
    float* out_q     = out_recon + (size_t)N_TOK * H_DIM;          // [B,Q,HR]
    float* out_idx   = out_q + (size_t)N_TOK * HR_DIM;             // [B,Q]
    float* out_loss  = out_idx + N_TOK;                            // scalar

    float *h, *z;
    cudaGetSymbolAddress((void**)&h, g_h);
    cudaGetSymbolAddress((void**)&z, g_z);

    // codebook norms + argmin init
    prep_kernel<<<CB_N, 128>>>(cb);

    // encoder
    sgemm_kernel<true ><<<dim3(H_DIM/BN,  N_TOK/BM), 256>>>(x, enc_w1, enc_b1, h, N_TOK, H_DIM,  H_DIM);
    sgemm_kernel<false><<<dim3(HR_DIM/BN, N_TOK/BM), 256>>>(h, enc_w2, enc_b2, z, N_TOK, HR_DIM, H_DIM);

    // vector-quantize: fused distance GEMM + argmin
    vq_kernel<<<dim3(CB_N/BN, N_TOK/BM), 256>>>(z, cb);
    gather_kernel<<<N_TOK, 128>>>(cb, out_q, out_idx);

    // decoder (input = quantized_st == gathered codebook rows)
    sgemm_kernel<true ><<<dim3(H_DIM/BN, N_TOK/BM), 256>>>(out_q, dec_w1, dec_b1, h, N_TOK, H_DIM, HR_DIM);
    sgemm_kernel<false><<<dim3(H_DIM/BN, N_TOK/BM), 256>>>(h, dec_w2, dec_b2, out_recon, N_TOK, H_DIM, H_DIM);

    // commit loss
    loss_kernel<<<1, 1024>>>(out_loss);
}

// round 3
// speedup vs baseline: 1.0209x; 1.0207x over previous
#include <cuda_runtime.h>
#include <cstdint>

// Problem constants
#define N_TOK  32768     // B*Q
#define H_DIM  1024
#define HR_DIM 512
#define CB_N   4096

// GEMM tiling
#define BM 128
#define BN 128
#define BK 16

// ---------------- scratch (device globals; no runtime allocation) ----------------
__device__ float g_h[(size_t)N_TOK * H_DIM];   // 134 MB: h (enc) then h2 (dec)
__device__ float g_z[(size_t)N_TOK * HR_DIM];  // 67 MB: pre-quant latent
__device__ float g_cbnorm[CB_N];               // ||e_c||^2
__device__ unsigned long long g_best[N_TOK];   // packed (ordered_d_key<<32 | idx)
__device__ float g_commit[N_TOK];              // per-row commit partial sums

// Monotonic float->uint mapping so unsigned compare == float compare
__device__ __forceinline__ unsigned long long pack_di(float d, unsigned idx) {
    unsigned b = __float_as_uint(d);
    unsigned key = b ^ ((unsigned)((int)b >> 31) | 0x80000000u);
    return ((unsigned long long)key << 32) | (unsigned long long)idx;
}

// ---------------- packed f32x2 helpers (sm_103a 2-wide fp32 FMA pipe) ----------------
__device__ __forceinline__ unsigned long long f2_pack(float lo, float hi) {
    unsigned long long r;
    asm("mov.b64 %0, {%1, %2};" : "=l"(r) : "f"(lo), "f"(hi));
    return r;
}
__device__ __forceinline__ unsigned long long f2_bcast(float x) {
    unsigned long long r;
    asm("mov.b64 %0, {%1, %1};" : "=l"(r) : "f"(x));
    return r;
}
__device__ __forceinline__ void f2_fma(unsigned long long& d,
                                       unsigned long long a, unsigned long long b) {
    asm("fma.rn.f32x2 %0, %1, %2, %0;" : "+l"(d) : "l"(a), "l"(b));
}
__device__ __forceinline__ void f2_unpack(unsigned long long v, float& lo, float& hi) {
    asm("mov.b64 {%0, %1}, %2;" : "=f"(lo), "=f"(hi) : "l"(v));
}

// ---------------- SGEMM: C[M,N] = op(A[M,K] @ B[K,N] + bias), op = relu? ----------------
// 256 threads, 128x128 tile, BK=16, 8x8 per thread (as 8x4 f32x2 pairs),
// double-buffered smem, packed FFMA2 inner loop.
template<bool RELU>
__global__ __launch_bounds__(256, 2)
void sgemm_kernel(const float* __restrict__ A, const float* __restrict__ B,
                  const float* __restrict__ bias, float* __restrict__ C,
                  int M, int N, int K)
{
    __shared__ __align__(16) float As[2][BK][BM];
    __shared__ __align__(16) float Bs[2][BK][BN];

    const int tid = threadIdx.x;
    const int bm = blockIdx.y * BM;
    const int bn = blockIdx.x * BN;
    const int tx = tid & 15;   // 16 col groups
    const int ty = tid >> 4;   // 16 row groups

    const int a_r = tid >> 2;          // 0..63 (+64 for second)
    const int a_k = (tid & 3) * 4;     // 0,4,8,12
    const int b_r = tid >> 5;          // 0..7 (+8 for second)
    const int b_c = (tid & 31) * 4;    // 0..124

    const float* Ap0 = A + (size_t)(bm + a_r)      * K + a_k;
    const float* Ap1 = A + (size_t)(bm + a_r + 64) * K + a_k;
    const float* Bp0 = B + (size_t)(b_r)     * N + bn + b_c;
    const float* Bp1 = B + (size_t)(b_r + 8) * N + bn + b_c;

    // acc pairs: acc2[i][jp] = (C[i][2jp], C[i][2jp+1])
    unsigned long long acc2[8][4];
    const unsigned long long z2 = f2_pack(0.0f, 0.0f);
    #pragma unroll
    for (int i = 0; i < 8; i++)
        #pragma unroll
        for (int j = 0; j < 4; j++) acc2[i][j] = z2;

    // prologue: tile 0
    float4 ar0 = *(const float4*)Ap0;
    float4 ar1 = *(const float4*)Ap1;
    float4 br0 = *(const float4*)Bp0;
    float4 br1 = *(const float4*)Bp1;

    As[0][a_k+0][a_r] = ar0.x;  As[0][a_k+1][a_r] = ar0.y;
    As[0][a_k+2][a_r] = ar0.z;  As[0][a_k+3][a_r] = ar0.w;
    As[0][a_k+0][a_r+64] = ar1.x;  As[0][a_k+1][a_r+64] = ar1.y;
    As[0][a_k+2][a_r+64] = ar1.z;  As[0][a_k+3][a_r+64] = ar1.w;
    *(float4*)&Bs[0][b_r][b_c]   = br0;
    *(float4*)&Bs[0][b_r+8][b_c] = br1;
    __syncthreads();

    const int nK = K / BK;
    int cur = 0;
    for (int kt = 0; kt < nK; kt++) {
        if (kt + 1 < nK) {
            const size_t koff = (size_t)(kt + 1) * BK;
            ar0 = *(const float4*)(Ap0 + koff);
            ar1 = *(const float4*)(Ap1 + koff);
            br0 = *(const float4*)(Bp0 + koff * N);
            br1 = *(const float4*)(Bp1 + koff * N);
        }
        #pragma unroll
        for (int k = 0; k < BK; k++) {
            float a[8];
            float4 bv0 = *(const float4*)&Bs[cur][k][tx*8];
            float4 bv1 = *(const float4*)&Bs[cur][k][tx*8+4];
            *(float4*)&a[0] = *(const float4*)&As[cur][k][ty*8];
            *(float4*)&a[4] = *(const float4*)&As[cur][k][ty*8+4];
            unsigned long long b2[4];
            b2[0] = f2_pack(bv0.x, bv0.y);
            b2[1] = f2_pack(bv0.z, bv0.w);
            b2[2] = f2_pack(bv1.x, bv1.y);
            b2[3] = f2_pack(bv1.z, bv1.w);
            #pragma unroll
            for (int i = 0; i < 8; i++) {
                const unsigned long long a2 = f2_bcast(a[i]);
                #pragma unroll
                for (int j = 0; j < 4; j++)
                    f2_fma(acc2[i][j], a2, b2[j]);
            }
        }
        if (kt + 1 < nK) {
            const int nxt = cur ^ 1;
            As[nxt][a_k+0][a_r] = ar0.x;  As[nxt][a_k+1][a_r] = ar0.y;
            As[nxt][a_k+2][a_r] = ar0.z;  As[nxt][a_k+3][a_r] = ar0.w;
            As[nxt][a_k+0][a_r+64] = ar1.x;  As[nxt][a_k+1][a_r+64] = ar1.y;
            As[nxt][a_k+2][a_r+64] = ar1.z;  As[nxt][a_k+3][a_r+64] = ar1.w;
            *(float4*)&Bs[nxt][b_r][b_c]   = br0;
            *(float4*)&Bs[nxt][b_r+8][b_c] = br1;
            __syncthreads();
            cur = nxt;
        }
    }

    // epilogue: bias (+relu), vectorized store
    #pragma unroll
    for (int i = 0; i < 8; i++) {
        const size_t rowoff = (size_t)(bm + ty*8 + i) * N;
        #pragma unroll
        for (int jp = 0; jp < 4; jp += 2) {
            const int col = bn + tx*8 + jp*2;
            float4 v;
            f2_unpack(acc2[i][jp],   v.x, v.y);
            f2_unpack(acc2[i][jp+1], v.z, v.w);
            v.x += bias[col+0];
            v.y += bias[col+1];
            v.z += bias[col+2];
            v.w += bias[col+3];
            if (RELU) {
                v.x = fmaxf(v.x, 0.0f); v.y = fmaxf(v.y, 0.0f);
                v.z = fmaxf(v.z, 0.0f); v.w = fmaxf(v.w, 0.0f);
            }
            *(float4*)&C[rowoff + col] = v;
        }
    }
}

// ---------------- VQ: fused NT-GEMM (z @ codebook^T) + argmin epilogue ----------------
__global__ __launch_bounds__(256, 2)
void vq_kernel(const float* __restrict__ Z, const float* __restrict__ CB)
{
    __shared__ __align__(16) float As[2][BK][BM];
    __shared__ __align__(16) float Bs[2][BK][BN];
    __shared__ unsigned long long red[BM];

    const int tid = threadIdx.x;
    const int bm = blockIdx.y * BM;   // token tile
    const int bn = blockIdx.x * BN;   // codebook tile
    const int tx = tid & 15;
    const int ty = tid >> 4;

    const int a_r = tid >> 2;
    const int a_k = (tid & 3) * 4;

    const float* Ap0 = Z  + (size_t)(bm + a_r)      * HR_DIM + a_k;
    const float* Ap1 = Z  + (size_t)(bm + a_r + 64) * HR_DIM + a_k;
    const float* Bp0 = CB + (size_t)(bn + a_r)      * HR_DIM + a_k;
    const float* Bp1 = CB + (size_t)(bn + a_r + 64) * HR_DIM + a_k;

    if (tid < BM) red[tid] = 0xFFFFFFFFFFFFFFFFull;

    unsigned long long acc2[8][4];
    const unsigned long long z2 = f2_pack(0.0f, 0.0f);
    #pragma unroll
    for (int i = 0; i < 8; i++)
        #pragma unroll
        for (int j = 0; j < 4; j++) acc2[i][j] = z2;

    float4 ar0 = *(const float4*)Ap0;
    float4 ar1 = *(const float4*)Ap1;
    float4 br0 = *(const float4*)Bp0;
    float4 br1 = *(const float4*)Bp1;

    As[0][a_k+0][a_r] = ar0.x;  As[0][a_k+1][a_r] = ar0.y;
    As[0][a_k+2][a_r] = ar0.z;  As[0][a_k+3][a_r] = ar0.w;
    As[0][a_k+0][a_r+64] = ar1.x;  As[0][a_k+1][a_r+64] = ar1.y;
    As[0][a_k+2][a_r+64] = ar1.z;  As[0][a_k+3][a_r+64] = ar1.w;
    Bs[0][a_k+0][a_r] = br0.x;  Bs[0][a_k+1][a_r] = br0.y;
    Bs[0][a_k+2][a_r] = br0.z;  Bs[0][a_k+3][a_r] = br0.w;
    Bs[0][a_k+0][a_r+64] = br1.x;  Bs[0][a_k+1][a_r+64] = br1.y;
    Bs[0][a_k+2][a_r+64] = br1.z;  Bs[0][a_k+3][a_r+64] = br1.w;
    __syncthreads();

    const int nK = HR_DIM / BK;   // 32
    int cur = 0;
    for (int kt = 0; kt < nK; kt++) {
        if (kt + 1 < nK) {
            const size_t koff = (size_t)(kt + 1) * BK;
            ar0 = *(const float4*)(Ap0 + koff);
            ar1 = *(const float4*)(Ap1 + koff);
            br0 = *(const float4*)(Bp0 + koff);
            br1 = *(const float4*)(Bp1 + koff);
        }
        #pragma unroll
        for (int k = 0; k < BK; k++) {
            float a[8];
            float4 bv0 = *(const float4*)&Bs[cur][k][tx*8];
            float4 bv1 = *(const float4*)&Bs[cur][k][tx*8+4];
            *(float4*)&a[0] = *(const float4*)&As[cur][k][ty*8];
            *(float4*)&a[4] = *(const float4*)&As[cur][k][ty*8+4];
            unsigned long long b2[4];
            b2[0] = f2_pack(bv0.x, bv0.y);
            b2[1] = f2_pack(bv0.z, bv0.w);
            b2[2] = f2_pack(bv1.x, bv1.y);
            b2[3] = f2_pack(bv1.z, bv1.w);
            #pragma unroll
            for (int i = 0; i < 8; i++) {
                const unsigned long long a2 = f2_bcast(a[i]);
                #pragma unroll
                for (int j = 0; j < 4; j++)
                    f2_fma(acc2[i][j], a2, b2[j]);
            }
        }
        if (kt + 1 < nK) {
            const int nxt = cur ^ 1;
            As[nxt][a_k+0][a_r] = ar0.x;  As[nxt][a_k+1][a_r] = ar0.y;
            As[nxt][a_k+2][a_r] = ar0.z;  As[nxt][a_k+3][a_r] = ar0.w;
            As[nxt][a_k+0][a_r+64] = ar1.x;  As[nxt][a_k+1][a_r+64] = ar1.y;
            As[nxt][a_k+2][a_r+64] = ar1.z;  As[nxt][a_k+3][a_r+64] = ar1.w;
            Bs[nxt][a_k+0][a_r] = br0.x;  Bs[nxt][a_k+1][a_r] = br0.y;
            Bs[nxt][a_k+2][a_r] = br0.z;  Bs[nxt][a_k+3][a_r] = br0.w;
            Bs[nxt][a_k+0][a_r+64] = br1.x;  Bs[nxt][a_k+1][a_r+64] = br1.y;
            Bs[nxt][a_k+2][a_r+64] = br1.z;  Bs[nxt][a_k+3][a_r+64] = br1.w;
            __syncthreads();
            cur = nxt;
        }
    }

    // epilogue: d = ||e||^2 - 2*(z.e); per-row argmin (first-occurrence ties)
    float cn[8];
    #pragma unroll
    for (int j = 0; j < 8; j++) cn[j] = __ldg(&g_cbnorm[bn + tx*8 + j]);

    #pragma unroll
    for (int i = 0; i < 8; i++) {
        float accf[8];
        #pragma unroll
        for (int jp = 0; jp < 4; jp++)
            f2_unpack(acc2[i][jp], accf[2*jp], accf[2*jp+1]);
        float bestd = cn[0] - 2.0f * accf[0];
        int   bestj = 0;
        #pragma unroll
        for (int j = 1; j < 8; j++) {
            float d = cn[j] - 2.0f * accf[j];
            if (d < bestd) { bestd = d; bestj = j; }
        }
        atomicMin(&red[ty*8 + i], pack_di(bestd, (unsigned)(bn + tx*8 + bestj)));
    }
    __syncthreads();
    if (tid < BM) atomicMin(&g_best[bm + tid], red[tid]);
}

// ---------------- codebook norms + argmin state init ----------------
__global__ void prep_kernel(const float* __restrict__ CB)
{
    const int row = blockIdx.x;      // CB_N blocks
    const int tid = threadIdx.x;     // 128 threads -> 128 float4 = 512 floats
    float4 v = ((const float4*)(CB + (size_t)row * HR_DIM))[tid];
    float s = v.x*v.x + v.y*v.y + v.z*v.z + v.w*v.w;
    #pragma unroll
    for (int o = 16; o; o >>= 1) s += __shfl_down_sync(0xFFFFFFFFu, s, o);
    __shared__ float ws[4];
    if ((tid & 31) == 0) ws[tid >> 5] = s;
    __syncthreads();
    if (tid == 0) g_cbnorm[row] = ws[0] + ws[1] + ws[2] + ws[3];

    const int g = row * 128 + tid;   // 524288 slots cover N_TOK
    if (g < N_TOK) g_best[g] = 0xFFFFFFFFFFFFFFFFull;
}

// ---------------- gather winner codebook row + per-row commit partial ----------------
__global__ void gather_kernel(const float* __restrict__ CB,
                              float* __restrict__ outq, float* __restrict__ outidx)
{
    const int row = blockIdx.x;      // N_TOK blocks
    const int tid = threadIdx.x;     // 128 threads
    const unsigned idx = (unsigned)(g_best[row] & 0xFFFFFFFFull);

    float4 ev = ((const float4*)(CB  + (size_t)idx * HR_DIM))[tid];
    float4 zv = ((const float4*)(g_z + (size_t)row * HR_DIM))[tid];
    ((float4*)(outq + (size_t)row * HR_DIM))[tid] = ev;

    const float dx = zv.x - ev.x, dy = zv.y - ev.y;
    const float dz = zv.z - ev.z, dw = zv.w - ev.w;
    float s = dx*dx + dy*dy + dz*dz + dw*dw;
    #pragma unroll
    for (int o = 16; o; o >>= 1) s += __shfl_down_sync(0xFFFFFFFFu, s, o);
    __shared__ float ws[4];
    if ((tid & 31) == 0) ws[tid >> 5] = s;
    __syncthreads();
    if (tid == 0) {
        g_commit[row] = ws[0] + ws[1] + ws[2] + ws[3];
        outidx[row] = (float)idx;
    }
}

// ---------------- deterministic commit-loss reduce ----------------
__global__ void loss_kernel(float* __restrict__ out_loss)
{
    __shared__ float ws[32];
    const int tid = threadIdx.x;     // 1024
    float s = 0.0f;
    for (int i = tid; i < N_TOK; i += 1024) s += g_commit[i];
    #pragma unroll
    for (int o = 16; o; o >>= 1) s += __shfl_down_sync(0xFFFFFFFFu, s, o);
    if ((tid & 31) == 0) ws[tid >> 5] = s;
    __syncthreads();
    if (tid < 32) {
        float t = ws[tid];
        #pragma unroll
        for (int o = 16; o; o >>= 1) t += __shfl_down_sync(0xFFFFFFFFu, t, o);
        if (tid == 0)
            out_loss[0] = 0.25f * t / (float)((size_t)N_TOK * HR_DIM);
    }
}

// ---------------- launcher ----------------
extern "C" void kernel_launch(void* const* d_in, const int* in_sizes, int n_in,
                              void* d_out, int out_size)
{
    const float* x      = (const float*)d_in[0];
    const float* enc_w1 = (const float*)d_in[1];
    const float* enc_b1 = (const float*)d_in[2];
    const float* enc_w2 = (const float*)d_in[3];
    const float* enc_b2 = (const float*)d_in[4];
    const float* cb     = (const float*)d_in[5];
    const float* dec_w1 = (const float*)d_in[6];
    const float* dec_b1 = (const float*)d_in[7];
    const float* dec_w2 = (const float*)d_in[8];
    const float* dec_b2 = (const float*)d_in[9];

    float* out       = (float*)d_out;
    float* out_recon = out;                                        // [B,Q,H]
    float* out_q     = out_recon + (size_t)N_TOK * H_DIM;          // [B,Q,HR]
    float* out_idx   = out_q + (size_t)N_TOK * HR_DIM;             // [B,Q]
    float* out_loss  = out_idx + N_TOK;                            // scalar

    float *h, *z;
    cudaGetSymbolAddress((void**)&h, g_h);
    cudaGetSymbolAddress((void**)&z, g_z);

    // codebook norms + argmin init
    prep_kernel<<<CB_N, 128>>>(cb);

    // encoder
    sgemm_kernel<true ><<<dim3(H_DIM/BN,  N_TOK/BM), 256>>>(x, enc_w1, enc_b1, h, N_TOK, H_DIM,  H_DIM);
    sgemm_kernel<false><<<dim3(HR_DIM/BN, N_TOK/BM), 256>>>(h, enc_w2, enc_b2, z, N_TOK, HR_DIM, H_DIM);

    // vector-quantize: fused distance GEMM + argmin
    vq_kernel<<<dim3(CB_N/BN, N_TOK/BM), 256>>>(z, cb);
    gather_kernel<<<N_TOK, 128>>>(cb, out_q, out_idx);

    // decoder (input = quantized_st == gathered codebook rows)
    sgemm_kernel<true ><<<dim3(H_DIM/BN, N_TOK/BM), 256>>>(out_q, dec_w1, dec_b1, h, N_TOK, H_DIM, HR_DIM);
    sgemm_kernel<false><<<dim3(H_DIM/BN, N_TOK/BM), 256>>>(h, dec_w2, dec_b2, out_recon, N_TOK, H_DIM, H_DIM);

    // commit loss
    loss_kernel<<<1, 1024>>>(out_loss);
}